// round 16
// baseline (speedup 1.0000x reference)
#include <cuda_runtime.h>
#include <cuda_fp16.h>
#include <cstdint>

// Problem constants
#define BB 4
#define SS 2048
#define HH 16
#define DD 1024
#define DK 64
#define MTOT (BB * SS)          // 8192

// score scale 1/sqrt(64) folded with log2(e) into Q at projection time.
#define QSCALE 0.1803368801111204f   // 0.125 * log2(e)

// Tiled layout: tile = 128 rows x 32 k (80B padded rows) = 10240 B
#define TB 10240
#define A_TILED_BYTES (MTOT / 128 * 32 * TB)   // 20971520
#define W_TILED_BYTES (DD / 128 * 32 * TB)     // 2621440

// ---------------------------------------------------------------------------
// Scratch (device globals — no runtime allocation allowed)
// ---------------------------------------------------------------------------
__device__ __align__(16) char g_qT[A_TILED_BYTES];
__device__ __align__(16) char g_kT[A_TILED_BYTES];
__device__ __align__(16) char g_vT[A_TILED_BYTES];
__device__ __align__(16) char g_ZT[A_TILED_BYTES];
__device__ __align__(16) char g_WqT[W_TILED_BYTES], g_WkT[W_TILED_BYTES];
__device__ __align__(16) char g_WvT[W_TILED_BYTES], g_WpT[W_TILED_BYTES];
// attention inputs: Q (pre-scaled), K, V — all single fp16
__device__ __half g_QP[MTOT * DD];
__device__ __half g_KP[MTOT * DD];
__device__ __half g_VP[MTOT * DD];

// ---------------------------------------------------------------------------
// PTX helpers
// ---------------------------------------------------------------------------
__device__ __forceinline__ uint32_t smem_u32(const void* p) {
    uint32_t a;
    asm("{ .reg .u64 t; cvta.to.shared.u64 t, %1; cvt.u32.u64 %0, t; }"
        : "=r"(a) : "l"(p));
    return a;
}

__device__ __forceinline__ float ex2f(float x) {
    float y;
    asm("ex2.approx.ftz.f32 %0, %1;" : "=f"(y) : "f"(x));
    return y;
}

__device__ __forceinline__ void ldsm4(uint32_t addr, uint32_t* r) {
    asm volatile("ldmatrix.sync.aligned.m8n8.x4.shared.b16 {%0,%1,%2,%3}, [%4];"
        : "=r"(r[0]), "=r"(r[1]), "=r"(r[2]), "=r"(r[3]) : "r"(addr));
}

__device__ __forceinline__ void ldsm4t(uint32_t addr, uint32_t* r) {
    asm volatile("ldmatrix.sync.aligned.m8n8.x4.trans.shared.b16 {%0,%1,%2,%3}, [%4];"
        : "=r"(r[0]), "=r"(r[1]), "=r"(r[2]), "=r"(r[3]) : "r"(addr));
}

__device__ __forceinline__ void mma16816(float* c, const uint32_t* a, const uint32_t* b) {
    asm volatile(
        "mma.sync.aligned.m16n8k16.row.col.f32.f16.f16.f32 "
        "{%0,%1,%2,%3}, {%4,%5,%6,%7}, {%8,%9}, {%0,%1,%2,%3};"
        : "+f"(c[0]), "+f"(c[1]), "+f"(c[2]), "+f"(c[3])
        : "r"(a[0]), "r"(a[1]), "r"(a[2]), "r"(a[3]), "r"(b[0]), "r"(b[1]));
}

__device__ __forceinline__ void cp16(uint32_t dst, const void* src) {
    asm volatile("cp.async.cg.shared.global [%0], [%1], 16;" :: "r"(dst), "l"(src));
}
#define CP_COMMIT asm volatile("cp.async.commit_group;" ::: "memory")
#define CP_WAIT1  asm volatile("cp.async.wait_group 1;" ::: "memory")
#define CP_WAIT0  asm volatile("cp.async.wait_group 0;" ::: "memory")

__device__ __forceinline__ void bulk_g2s(uint32_t dst, const void* src,
                                         uint32_t bytes, uint32_t mbar) {
    asm volatile(
        "cp.async.bulk.shared::cluster.global.mbarrier::complete_tx::bytes "
        "[%0], [%1], %2, [%3];"
        :: "r"(dst), "l"(src), "r"(bytes), "r"(mbar) : "memory");
}

#define MBARRIER_INIT(mbar, count) \
    asm volatile("mbarrier.init.shared.b64 [%0], %1;" \
        :: "r"((uint32_t)(mbar)), "r"((uint32_t)(count)) : "memory")

#define MBARRIER_EXPECT_TX(mbar, bytes) \
    asm volatile("mbarrier.arrive.expect_tx.shared.b64 _, [%0], %1;" \
        :: "r"((uint32_t)(mbar)), "r"((uint32_t)(bytes)) : "memory")

#define MBARRIER_WAIT_PARITY(mbar_smem_addr, phase_parity) do { \
    uint32_t _mbar = (uint32_t)(mbar_smem_addr); \
    uint32_t _parity = (uint32_t)(phase_parity); \
    uint32_t _done; \
    asm volatile( \
        "{\n\t.reg .pred p;\n\t" \
        "mbarrier.try_wait.parity.acquire.cta.shared::cta.b64 p, [%1], %2;\n\t" \
        "selp.b32 %0, 1, 0, p;\n\t}" \
        : "=r"(_done) : "r"(_mbar), "r"(_parity) : "memory"); \
    if (!_done) { \
        asm volatile( \
            "{\n\t.reg .pred P1;\n\t" \
            "WAIT_LOOP_%=:\n\t" \
            "mbarrier.try_wait.parity.acquire.cta.shared::cta.b64 P1, [%0], %1, 0x989680;\n\t" \
            "@P1 bra.uni WAIT_DONE_%=;\n\t" \
            "bra.uni WAIT_LOOP_%=;\n\t" \
            "WAIT_DONE_%=:\n\t}" \
            :: "r"(_mbar), "r"(_parity) : "memory"); \
    } \
} while (0)

__device__ __forceinline__ uint32_t pack2h(float a, float b) {
    __half2 hh = __floats2half2_rn(a, b);
    return *(uint32_t*)&hh;
}

// ---------------------------------------------------------------------------
// cvt: fp32 [rows,1024] -> tiled single fp16.  z selects the tensor.
// ---------------------------------------------------------------------------
__device__ __forceinline__ void cvt_one(const float* __restrict__ x,
                                        char* __restrict__ o, int idx) {
    const int m  = idx >> 7;
    const int k0 = (idx & 127) << 3;
    const float4 a = *(const float4*)(x + (size_t)m * DD + k0);
    const float4 b = *(const float4*)(x + (size_t)m * DD + k0 + 4);
    uint32_t H[4] = { pack2h(a.x, a.y), pack2h(a.z, a.w),
                      pack2h(b.x, b.y), pack2h(b.z, b.w) };
    const size_t off = (size_t)((m >> 7) * 32 + (k0 >> 5)) * TB
                     + (m & 127) * 80 + (k0 & 31) * 2;
    *(uint4*)(o + off) = *(uint4*)H;
}

__global__ __launch_bounds__(256)
void cvt3(const float* x0, const float* x1, const float* x2,
          char* o0, char* o1, char* o2)
{
    const int z = blockIdx.z;
    const float* x = (z == 0) ? x0 : (z == 1) ? x1 : x2;
    char* o = (z == 0) ? o0 : (z == 1) ? o1 : o2;
    cvt_one(x, o, blockIdx.x * 256 + threadIdx.x);
}

__global__ __launch_bounds__(256)
void cvt4(const float* x0, const float* x1, const float* x2, const float* x3,
          char* o0, char* o1, char* o2, char* o3)
{
    const int z = blockIdx.z;
    const float* x = (z == 0) ? x0 : (z == 1) ? x1 : (z == 2) ? x2 : x3;
    char* o = (z == 0) ? o0 : (z == 1) ? o1 : (z == 2) ? o2 : o3;
    cvt_one(x, o, blockIdx.x * 256 + threadIdx.x);
}

// ---------------------------------------------------------------------------
// Fused QKV projection GEMM, CTA tile 256x128 (halved W L2 traffic).
// 512 threads = 16 warps (4m x 4n), warp tile 64x32, 3-stage bulk, 1 CTA/SM.
// grid (8, 32, 3): z = 0(Q, scaled), 1(K), 2(V); all emit single fp16.
// ---------------------------------------------------------------------------
#define AT1 (2 * TB)                  // 256-row A tile = two 128-row regions
#define GST1 (AT1 + TB)               // 30720 per stage
#define SMEM_G1 (3 * GST1 + 64)       // 92224

struct QKVArgs {
    const char* A[3];
    const char* W[3];
    const float* bias[3];
    __half* O[3];
};

__global__ __launch_bounds__(512, 1)
void gemm_qkv(QKVArgs args)
{
    extern __shared__ __align__(16) char smem[];
    const uint32_t sb = smem_u32(smem);
    const uint32_t mbar = sb + 3 * GST1;

    const int z = blockIdx.z;
    const char* At = args.A[z];
    const char* Wt = args.W[z];
    const float* bias = args.bias[z];
    __half* O = args.O[z];

    const int tid  = threadIdx.x;
    const int lane = tid & 31;
    const int wid  = tid >> 5;
    const int wm   = wid & 3;      // 0..3 (64-row group)
    const int wn   = wid >> 2;     // 0..3 (32-col group)
    const int m0 = blockIdx.y * 256;
    const int n0 = blockIdx.x * 128;

    if (tid == 0) {
        MBARRIER_INIT(mbar, 1);
        MBARRIER_INIT(mbar + 8, 1);
        MBARRIER_INIT(mbar + 16, 1);
    }
    __syncthreads();

    auto issue = [&](int ks) {
        const int s = ks % 3;
        const uint32_t mb_ = mbar + s * 8;
        MBARRIER_EXPECT_TX(mb_, (uint32_t)GST1);
        bulk_g2s(sb + s * GST1,
                 At + (size_t)((2 * blockIdx.y) * 32 + ks) * TB, TB, mb_);
        bulk_g2s(sb + s * GST1 + TB,
                 At + (size_t)((2 * blockIdx.y + 1) * 32 + ks) * TB, TB, mb_);
        bulk_g2s(sb + s * GST1 + AT1,
                 Wt + (size_t)(blockIdx.x * 32 + ks) * TB, TB, mb_);
    };

    float acc[4][4][4];
#pragma unroll
    for (int mi = 0; mi < 4; mi++)
#pragma unroll
        for (int ni = 0; ni < 4; ni++)
#pragma unroll
            for (int j = 0; j < 4; j++) acc[mi][ni][j] = 0.0f;

    if (tid == 0) { issue(0); issue(1); }
    int ph0 = 0, ph1 = 0, ph2 = 0;

    for (int ks = 0; ks < 32; ks++) {
        if (tid == 0 && ks + 2 < 32) issue(ks + 2);

        const int s = ks % 3;
        if (s == 0)      { MBARRIER_WAIT_PARITY(mbar,      ph0); ph0 ^= 1; }
        else if (s == 1) { MBARRIER_WAIT_PARITY(mbar + 8,  ph1); ph1 ^= 1; }
        else             { MBARRIER_WAIT_PARITY(mbar + 16, ph2); ph2 ^= 1; }

        const uint32_t sA = sb + s * GST1;      // 2 x 128-row regions
        const uint32_t sW = sA + AT1;

#pragma unroll
        for (int kk = 0; kk < 32; kk += 16) {
            uint32_t bw[4][2];
#pragma unroll
            for (int np = 0; np < 2; np++) {
                const int g    = lane >> 3;
                const int brow = wn * 32 + np * 16 + ((g >> 1) << 3) + (lane & 7);
                const int bk   = kk + ((g & 1) << 3);
                uint32_t r[4];
                ldsm4(sW + brow * 80 + bk * 2, r);
                bw[2 * np][0] = r[0]; bw[2 * np][1] = r[1];
                bw[2 * np + 1][0] = r[2]; bw[2 * np + 1][1] = r[3];
            }
            const int arow_off = (lane & 15);
            const int ak = kk + ((lane >> 4) << 3);
#pragma unroll
            for (int mi = 0; mi < 4; mi++) {
                const int arow = wm * 64 + mi * 16 + arow_off;   // 0..255
                const uint32_t aaddr = sA + (arow >> 7) * TB
                                     + (arow & 127) * 80 + ak * 2;
                uint32_t af[4];
                ldsm4(aaddr, af);
#pragma unroll
                for (int ni = 0; ni < 4; ni++)
                    mma16816(acc[mi][ni], af, bw[ni]);
            }
        }
        __syncthreads();
    }

#pragma unroll
    for (int mi = 0; mi < 4; mi++) {
#pragma unroll
        for (int ni = 0; ni < 4; ni++) {
            const int row0 = m0 + wm * 64 + mi * 16 + (lane >> 2);
            const int col  = n0 + wn * 32 + ni * 8 + 2 * (lane & 3);
            const float b0 = __ldg(bias + col);
            const float b1 = __ldg(bias + col + 1);
            float v00 = acc[mi][ni][0] + b0, v01 = acc[mi][ni][1] + b1;
            float v10 = acc[mi][ni][2] + b0, v11 = acc[mi][ni][3] + b1;
            if (z == 0) {       // Q: fold softmax scale * log2(e)
                v00 *= QSCALE; v01 *= QSCALE; v10 *= QSCALE; v11 *= QSCALE;
            }
            const int h = col >> 6, k = col & 63;
            {
                const int b = row0 >> 11, srow = row0 & 2047;
                const size_t o = (((size_t)b * HH + h) * SS + srow) * DK + k;
                *(uint32_t*)(O + o) = pack2h(v00, v01);
            }
            {
                const int r1 = row0 + 8;
                const int b = r1 >> 11, srow = r1 & 2047;
                const size_t o = (((size_t)b * HH + h) * SS + srow) * DK + k;
                *(uint32_t*)(O + o) = pack2h(v10, v11);
            }
        }
    }
}

// ---------------------------------------------------------------------------
// Output projection GEMM: C = Z x Wp^T + bias, single-fp16 Z (1 MMA/chunk),
// 3-stage bulk pipeline (2 x 10KB per stage), fp32 row-major out.
// ---------------------------------------------------------------------------
#define GST2 (2 * TB)                 // 20480
#define SMEM_G2 (3 * GST2 + 64)       // 61504

__global__ __launch_bounds__(256, 2)
void gemm_out(const char* __restrict__ At, const char* __restrict__ Wt,
              const float* __restrict__ bias, float* __restrict__ Cf)
{
    extern __shared__ __align__(16) char smem[];
    const uint32_t sb = smem_u32(smem);
    const uint32_t mbar = sb + 3 * GST2;

    const int tid  = threadIdx.x;
    const int lane = tid & 31;
    const int wid  = tid >> 5;
    const int wm   = wid & 1;
    const int wn   = wid >> 1;
    const int m0 = blockIdx.y * 128;
    const int n0 = blockIdx.x * 128;

    if (tid == 0) {
        MBARRIER_INIT(mbar, 1);
        MBARRIER_INIT(mbar + 8, 1);
        MBARRIER_INIT(mbar + 16, 1);
    }
    __syncthreads();

    auto issue = [&](int ks) {
        const int s = ks % 3;
        const uint32_t mb_ = mbar + s * 8;
        MBARRIER_EXPECT_TX(mb_, (uint32_t)GST2);
        bulk_g2s(sb + s * GST2,      At + (size_t)(blockIdx.y * 32 + ks) * TB, TB, mb_);
        bulk_g2s(sb + s * GST2 + TB, Wt + (size_t)(blockIdx.x * 32 + ks) * TB, TB, mb_);
    };

    float acc[4][4][4];
#pragma unroll
    for (int mi = 0; mi < 4; mi++)
#pragma unroll
        for (int ni = 0; ni < 4; ni++)
#pragma unroll
            for (int j = 0; j < 4; j++) acc[mi][ni][j] = 0.0f;

    if (tid == 0) { issue(0); issue(1); }
    int ph0 = 0, ph1 = 0, ph2 = 0;

    for (int ks = 0; ks < 32; ks++) {
        if (tid == 0 && ks + 2 < 32) issue(ks + 2);

        const int s = ks % 3;
        if (s == 0)      { MBARRIER_WAIT_PARITY(mbar,      ph0); ph0 ^= 1; }
        else if (s == 1) { MBARRIER_WAIT_PARITY(mbar + 8,  ph1); ph1 ^= 1; }
        else             { MBARRIER_WAIT_PARITY(mbar + 16, ph2); ph2 ^= 1; }

        const uint32_t sA = sb + s * GST2;
        const uint32_t sW = sA + TB;

#pragma unroll
        for (int kk = 0; kk < 32; kk += 16) {
            uint32_t bw[4][2];
#pragma unroll
            for (int np = 0; np < 2; np++) {
                const int g    = lane >> 3;
                const int brow = wn * 32 + np * 16 + ((g >> 1) << 3) + (lane & 7);
                const int bk   = kk + ((g & 1) << 3);
                uint32_t r[4];
                ldsm4(sW + brow * 80 + bk * 2, r);
                bw[2 * np][0] = r[0]; bw[2 * np][1] = r[1];
                bw[2 * np + 1][0] = r[2]; bw[2 * np + 1][1] = r[3];
            }
            const int arow_off = (lane & 15);
            const int ak = kk + ((lane >> 4) << 3);
#pragma unroll
            for (int mi = 0; mi < 4; mi++) {
                const int arow = wm * 64 + mi * 16 + arow_off;
                uint32_t af[4];
                ldsm4(sA + arow * 80 + ak * 2, af);
#pragma unroll
                for (int ni = 0; ni < 4; ni++)
                    mma16816(acc[mi][ni], af, bw[ni]);
            }
        }
        __syncthreads();
    }

#pragma unroll
    for (int mi = 0; mi < 4; mi++) {
#pragma unroll
        for (int ni = 0; ni < 4; ni++) {
            const int row0 = m0 + wm * 64 + mi * 16 + (lane >> 2);
            const int col  = n0 + wn * 32 + ni * 8 + 2 * (lane & 3);
            const float b0 = __ldg(bias + col);
            const float b1 = __ldg(bias + col + 1);
            *(float2*)(Cf + (size_t)row0 * DD + col) =
                make_float2(acc[mi][ni][0] + b0, acc[mi][ni][1] + b1);
            *(float2*)(Cf + (size_t)(row0 + 8) * DD + col) =
                make_float2(acc[mi][ni][2] + b0, acc[mi][ni][3] + b1);
        }
    }
}

// ---------------------------------------------------------------------------
// Causal flash attention: single-fp16 Q (1 MMA QK), single-fp16 P (1 MMA PV),
// fp32 ex2 softmax, single-fp16 Z epilogue.  4 CTAs/SM.
// ---------------------------------------------------------------------------
#define ROWB 144
#define KVTILE (64 * ROWB)
#define STGATT (2 * KVTILE)
#define SMEM_ATT (2 * STGATT)

__global__ __launch_bounds__(128, 4)
void attn_mma()
{
    extern __shared__ __align__(16) char smem[];
    const uint32_t sb = smem_u32(smem);
    const int tid  = threadIdx.x;
    const int lane = tid & 31;
    const int w    = tid >> 5;
    const int qb   = gridDim.x - 1 - blockIdx.x;   // big tiles first
    const int bh   = blockIdx.y;

    const size_t hoff = (size_t)bh * SS * DK;
    const __half* kvsrc[2] = { g_KP + hoff, g_VP + hoff };

    auto load_kv = [&](int kb, int stage) {
        const size_t base = (size_t)kb * 64 * DK;
#pragma unroll
        for (int i = 0; i < 8; i++) {
            const int c   = tid + i * 128;
            const int t   = c >> 9;
            const int cc  = c & 511;
            const int row = cc >> 3;
            const int ch  = cc & 7;
            cp16(sb + stage * STGATT + t * KVTILE + row * ROWB + ch * 16,
                 kvsrc[t] + base + row * DK + ch * 8);
        }
    };

    // prologue: Q (single tile) into stage-1 area, KV block 0 into stage 0
    {
        const __half* qsrc = g_QP + hoff + (size_t)qb * 64 * DK;
#pragma unroll
        for (int i = 0; i < 4; i++) {
            const int c   = tid + i * 128;   // 0..511
            const int row = c >> 3;
            const int ch  = c & 7;
            cp16(sb + STGATT + row * ROWB + ch * 16, qsrc + row * DK + ch * 8);
        }
    }
    CP_COMMIT;
    load_kv(0, 0);
    CP_COMMIT;
    CP_WAIT1;
    __syncthreads();

    uint32_t qf[4][4];
#pragma unroll
    for (int kc = 0; kc < 4; kc++) {
        const int row = w * 16 + (lane & 15);
        const int k   = kc * 16 + ((lane >> 4) << 3);
        ldsm4(sb + STGATT + row * ROWB + k * 2, qf[kc]);
    }
    __syncthreads();

    float co[8][4];
#pragma unroll
    for (int n = 0; n < 8; n++)
#pragma unroll
        for (int j = 0; j < 4; j++) co[n][j] = 0.0f;
    float m0v = -1e30f, m1v = -1e30f, l0 = 0.0f, l1 = 0.0f;

    for (int kb = 0; kb <= qb; kb++) {
        CP_WAIT0;
        __syncthreads();
        if (kb < qb) {
            load_kv(kb + 1, (kb + 1) & 1);
            CP_COMMIT;
        }

        const uint32_t stb = sb + (kb & 1) * STGATT;

        float c[8][4];
#pragma unroll
        for (int n = 0; n < 8; n++)
#pragma unroll
            for (int j = 0; j < 4; j++) c[n][j] = 0.0f;

#pragma unroll
        for (int kc = 0; kc < 4; kc++) {
            uint32_t kf[8][2];
#pragma unroll
            for (int p = 0; p < 4; p++) {
                const int g    = lane >> 3;
                const int brow = p * 16 + ((g >> 1) << 3) + (lane & 7);
                const int bk   = kc * 16 + ((g & 1) << 3);
                uint32_t r[4];
                ldsm4(stb + brow * ROWB + bk * 2, r);
                kf[2 * p][0] = r[0]; kf[2 * p][1] = r[1];
                kf[2 * p + 1][0] = r[2]; kf[2 * p + 1][1] = r[3];
            }
#pragma unroll
            for (int n = 0; n < 8; n++)
                mma16816(c[n], qf[kc], kf[n]);
        }

        // ---- softmax in log2 domain (scale pre-folded into Q) ----
        const bool diag = (kb == qb);
        const int r0 = lane >> 2, r1 = r0 + 8;
        const int rowloc = w * 16;
        float mx0 = -1e30f, mx1 = -1e30f;
#pragma unroll
        for (int n = 0; n < 8; n++) {
            if (diag) {
#pragma unroll
                for (int j = 0; j < 4; j++) {
                    const int col = n * 8 + 2 * (lane & 3) + (j & 1);
                    const int row = rowloc + ((j < 2) ? r0 : r1);
                    if (col > row) c[n][j] = -1e30f;
                }
            }
            mx0 = fmaxf(mx0, fmaxf(c[n][0], c[n][1]));
            mx1 = fmaxf(mx1, fmaxf(c[n][2], c[n][3]));
        }
        mx0 = fmaxf(mx0, __shfl_xor_sync(0xffffffff, mx0, 1));
        mx0 = fmaxf(mx0, __shfl_xor_sync(0xffffffff, mx0, 2));
        mx1 = fmaxf(mx1, __shfl_xor_sync(0xffffffff, mx1, 1));
        mx1 = fmaxf(mx1, __shfl_xor_sync(0xffffffff, mx1, 2));

        const float mn0 = fmaxf(m0v, mx0), mn1 = fmaxf(m1v, mx1);
        const float cor0 = ex2f(m0v - mn0), cor1 = ex2f(m1v - mn1);
        m0v = mn0; m1v = mn1;

        float s0 = 0.0f, s1 = 0.0f;
#pragma unroll
        for (int n = 0; n < 8; n++) {
            c[n][0] = ex2f(c[n][0] - mn0);
            c[n][1] = ex2f(c[n][1] - mn0);
            c[n][2] = ex2f(c[n][2] - mn1);
            c[n][3] = ex2f(c[n][3] - mn1);
            s0 += c[n][0] + c[n][1];
            s1 += c[n][2] + c[n][3];
        }
        s0 += __shfl_xor_sync(0xffffffff, s0, 1);
        s0 += __shfl_xor_sync(0xffffffff, s0, 2);
        s1 += __shfl_xor_sync(0xffffffff, s1, 1);
        s1 += __shfl_xor_sync(0xffffffff, s1, 2);
        l0 = l0 * cor0 + s0;
        l1 = l1 * cor1 + s1;
#pragma unroll
        for (int n = 0; n < 8; n++) {
            co[n][0] *= cor0; co[n][1] *= cor0;
            co[n][2] *= cor1; co[n][3] *= cor1;
        }

        // ---- pack P as single fp16 A-fragments ----
        uint32_t pa[4][4];
#pragma unroll
        for (int kc = 0; kc < 4; kc++) {
            pa[kc][0] = pack2h(c[2 * kc][0],     c[2 * kc][1]);
            pa[kc][1] = pack2h(c[2 * kc][2],     c[2 * kc][3]);
            pa[kc][2] = pack2h(c[2 * kc + 1][0], c[2 * kc + 1][1]);
            pa[kc][3] = pack2h(c[2 * kc + 1][2], c[2 * kc + 1][3]);
        }

#pragma unroll
        for (int kc = 0; kc < 4; kc++) {
            uint32_t vf[8][2];
#pragma unroll
            for (int dp = 0; dp < 4; dp++) {
                const int g    = lane >> 3;
                const int j    = lane & 7;
                const int srow = kc * 16 + ((g & 1) << 3) + j;
                const int dcol = dp * 16 + ((g >> 1) << 3);
                uint32_t r[4];
                ldsm4t(stb + KVTILE + srow * ROWB + dcol * 2, r);
                vf[2 * dp][0] = r[0]; vf[2 * dp][1] = r[1];
                vf[2 * dp + 1][0] = r[2]; vf[2 * dp + 1][1] = r[3];
            }
#pragma unroll
            for (int n = 0; n < 8; n++)
                mma16816(co[n], pa[kc], vf[n]);
        }
    }

    // epilogue: write Z tiled as single fp16 for the output GEMM
    const float i0 = 1.0f / l0, i1 = 1.0f / l1;
    const int b  = bh >> 4;
    const int hh = bh & 15;
    const int q0 = qb * 64 + w * 16 + (lane >> 2);
#pragma unroll
    for (int n = 0; n < 8; n++) {
        const int dk  = n * 8 + 2 * (lane & 3);
        const int col = hh * 64 + dk;
        const int mA = b * SS + q0;
        const int mB = mA + 8;
        const size_t oA = (size_t)((mA >> 7) * 32 + (col >> 5)) * TB
                        + (mA & 127) * 80 + (col & 31) * 2;
        const size_t oB = (size_t)((mB >> 7) * 32 + (col >> 5)) * TB
                        + (mB & 127) * 80 + (col & 31) * 2;
        *(uint32_t*)(g_ZT + oA) = pack2h(co[n][0] * i0, co[n][1] * i0);
        *(uint32_t*)(g_ZT + oB) = pack2h(co[n][2] * i1, co[n][3] * i1);
    }
}

// ---------------------------------------------------------------------------
// Launch
// ---------------------------------------------------------------------------
extern "C" void kernel_launch(void* const* d_in, const int* in_sizes, int n_in,
                              void* d_out, int out_size)
{
    const float* query = (const float*)d_in[0];
    const float* key   = (const float*)d_in[1];
    const float* value = (const float*)d_in[2];
    const float* Wq    = (const float*)d_in[3];
    const float* bq    = (const float*)d_in[4];
    const float* Wk    = (const float*)d_in[5];
    const float* bk    = (const float*)d_in[6];
    const float* Wv    = (const float*)d_in[7];
    const float* bv    = (const float*)d_in[8];
    const float* Wp    = (const float*)d_in[9];
    const float* bp    = (const float*)d_in[10];
    // d_in[11] = mask (statically causal -> applied analytically)

    char *qT, *kT, *vT, *ZT, *WqT, *WkT, *WvT, *WpT;
    __half *QP, *KP, *VP;
    cudaGetSymbolAddress((void**)&qT, g_qT);
    cudaGetSymbolAddress((void**)&kT, g_kT);
    cudaGetSymbolAddress((void**)&vT, g_vT);
    cudaGetSymbolAddress((void**)&ZT, g_ZT);
    cudaGetSymbolAddress((void**)&WqT, g_WqT); cudaGetSymbolAddress((void**)&WkT, g_WkT);
    cudaGetSymbolAddress((void**)&WvT, g_WvT); cudaGetSymbolAddress((void**)&WpT, g_WpT);
    cudaGetSymbolAddress((void**)&QP, g_QP);
    cudaGetSymbolAddress((void**)&KP, g_KP);
    cudaGetSymbolAddress((void**)&VP, g_VP);

    cudaFuncSetAttribute(gemm_qkv, cudaFuncAttributeMaxDynamicSharedMemorySize, SMEM_G1);
    cudaFuncSetAttribute(gemm_out, cudaFuncAttributeMaxDynamicSharedMemorySize, SMEM_G2);
    cudaFuncSetAttribute(attn_mma, cudaFuncAttributeMaxDynamicSharedMemorySize, SMEM_ATT);

    QKVArgs qa;
    qa.A[0] = qT;  qa.A[1] = kT;  qa.A[2] = vT;
    qa.W[0] = WqT; qa.W[1] = WkT; qa.W[2] = WvT;
    qa.bias[0] = bq; qa.bias[1] = bk; qa.bias[2] = bv;
    qa.O[0] = QP; qa.O[1] = KP; qa.O[2] = VP;

    cvt4<<<dim3(DD * DD / 8 / 256, 1, 4), 256>>>(Wq, Wk, Wv, Wp,
                                                 WqT, WkT, WvT, WpT);
    cvt3<<<dim3(MTOT * DD / 8 / 256, 1, 3), 256>>>(query, key, value,
                                                   qT, kT, vT);
    gemm_qkv<<<dim3(DD / 128, MTOT / 256, 3), 512, SMEM_G1>>>(qa);
    attn_mma<<<dim3(SS / 64, BB * HH), 128, SMEM_ATT>>>();
    gemm_out<<<dim3(DD / 128, MTOT / 128), 256, SMEM_G2>>>(ZT, WpT, bp,
                                                           (float*)d_out);
}

// round 17
// speedup vs baseline: 1.1110x; 1.1110x over previous
#include <cuda_runtime.h>
#include <cuda_fp16.h>
#include <cstdint>

// Problem constants
#define BB 4
#define SS 2048
#define HH 16
#define DD 1024
#define DK 64
#define MTOT (BB * SS)          // 8192

// score scale 1/sqrt(64) folded with log2(e) into Q at projection time.
#define QSCALE 0.1803368801111204f   // 0.125 * log2(e)

// Tiled layout: tile = 128 rows x 32 k (80B padded rows) = 10240 B
#define TB 10240
#define A_TILED_BYTES (MTOT / 128 * 32 * TB)   // 20971520
#define W_TILED_BYTES (DD / 128 * 32 * TB)     // 2621440

// ---------------------------------------------------------------------------
// Scratch (device globals — no runtime allocation allowed)
// ---------------------------------------------------------------------------
__device__ __align__(16) char g_qT[A_TILED_BYTES];
__device__ __align__(16) char g_kT[A_TILED_BYTES];
__device__ __align__(16) char g_vT[A_TILED_BYTES];
__device__ __align__(16) char g_ZT[A_TILED_BYTES];
__device__ __align__(16) char g_WqT[W_TILED_BYTES], g_WkT[W_TILED_BYTES];
__device__ __align__(16) char g_WvT[W_TILED_BYTES], g_WpT[W_TILED_BYTES];
// attention inputs: Q (pre-scaled), K, V — all single fp16
__device__ __half g_QP[MTOT * DD];
__device__ __half g_KP[MTOT * DD];
__device__ __half g_VP[MTOT * DD];

// ---------------------------------------------------------------------------
// PTX helpers
// ---------------------------------------------------------------------------
__device__ __forceinline__ uint32_t smem_u32(const void* p) {
    uint32_t a;
    asm("{ .reg .u64 t; cvta.to.shared.u64 t, %1; cvt.u32.u64 %0, t; }"
        : "=r"(a) : "l"(p));
    return a;
}

__device__ __forceinline__ float ex2f(float x) {
    float y;
    asm("ex2.approx.ftz.f32 %0, %1;" : "=f"(y) : "f"(x));
    return y;
}

__device__ __forceinline__ void ldsm4(uint32_t addr, uint32_t* r) {
    asm volatile("ldmatrix.sync.aligned.m8n8.x4.shared.b16 {%0,%1,%2,%3}, [%4];"
        : "=r"(r[0]), "=r"(r[1]), "=r"(r[2]), "=r"(r[3]) : "r"(addr));
}

__device__ __forceinline__ void ldsm4t(uint32_t addr, uint32_t* r) {
    asm volatile("ldmatrix.sync.aligned.m8n8.x4.trans.shared.b16 {%0,%1,%2,%3}, [%4];"
        : "=r"(r[0]), "=r"(r[1]), "=r"(r[2]), "=r"(r[3]) : "r"(addr));
}

__device__ __forceinline__ void mma16816(float* c, const uint32_t* a, const uint32_t* b) {
    asm volatile(
        "mma.sync.aligned.m16n8k16.row.col.f32.f16.f16.f32 "
        "{%0,%1,%2,%3}, {%4,%5,%6,%7}, {%8,%9}, {%0,%1,%2,%3};"
        : "+f"(c[0]), "+f"(c[1]), "+f"(c[2]), "+f"(c[3])
        : "r"(a[0]), "r"(a[1]), "r"(a[2]), "r"(a[3]), "r"(b[0]), "r"(b[1]));
}

__device__ __forceinline__ void cp16(uint32_t dst, const void* src) {
    asm volatile("cp.async.cg.shared.global [%0], [%1], 16;" :: "r"(dst), "l"(src));
}
#define CP_COMMIT asm volatile("cp.async.commit_group;" ::: "memory")
#define CP_WAIT1  asm volatile("cp.async.wait_group 1;" ::: "memory")
#define CP_WAIT0  asm volatile("cp.async.wait_group 0;" ::: "memory")

__device__ __forceinline__ void bulk_g2s(uint32_t dst, const void* src,
                                         uint32_t bytes, uint32_t mbar) {
    asm volatile(
        "cp.async.bulk.shared::cluster.global.mbarrier::complete_tx::bytes "
        "[%0], [%1], %2, [%3];"
        :: "r"(dst), "l"(src), "r"(bytes), "r"(mbar) : "memory");
}

#define MBARRIER_INIT(mbar, count) \
    asm volatile("mbarrier.init.shared.b64 [%0], %1;" \
        :: "r"((uint32_t)(mbar)), "r"((uint32_t)(count)) : "memory")

#define MBARRIER_EXPECT_TX(mbar, bytes) \
    asm volatile("mbarrier.arrive.expect_tx.shared.b64 _, [%0], %1;" \
        :: "r"((uint32_t)(mbar)), "r"((uint32_t)(bytes)) : "memory")

#define MBARRIER_WAIT_PARITY(mbar_smem_addr, phase_parity) do { \
    uint32_t _mbar = (uint32_t)(mbar_smem_addr); \
    uint32_t _parity = (uint32_t)(phase_parity); \
    uint32_t _done; \
    asm volatile( \
        "{\n\t.reg .pred p;\n\t" \
        "mbarrier.try_wait.parity.acquire.cta.shared::cta.b64 p, [%1], %2;\n\t" \
        "selp.b32 %0, 1, 0, p;\n\t}" \
        : "=r"(_done) : "r"(_mbar), "r"(_parity) : "memory"); \
    if (!_done) { \
        asm volatile( \
            "{\n\t.reg .pred P1;\n\t" \
            "WAIT_LOOP_%=:\n\t" \
            "mbarrier.try_wait.parity.acquire.cta.shared::cta.b64 P1, [%0], %1, 0x989680;\n\t" \
            "@P1 bra.uni WAIT_DONE_%=;\n\t" \
            "bra.uni WAIT_LOOP_%=;\n\t" \
            "WAIT_DONE_%=:\n\t}" \
            :: "r"(_mbar), "r"(_parity) : "memory"); \
    } \
} while (0)

__device__ __forceinline__ uint32_t pack2h(float a, float b) {
    __half2 hh = __floats2half2_rn(a, b);
    return *(uint32_t*)&hh;
}

// ---------------------------------------------------------------------------
// cvt: fp32 [rows,1024] -> tiled single fp16.  z selects the tensor.
// ---------------------------------------------------------------------------
__device__ __forceinline__ void cvt_one(const float* __restrict__ x,
                                        char* __restrict__ o, int idx) {
    const int m  = idx >> 7;
    const int k0 = (idx & 127) << 3;
    const float4 a = *(const float4*)(x + (size_t)m * DD + k0);
    const float4 b = *(const float4*)(x + (size_t)m * DD + k0 + 4);
    uint32_t H[4] = { pack2h(a.x, a.y), pack2h(a.z, a.w),
                      pack2h(b.x, b.y), pack2h(b.z, b.w) };
    const size_t off = (size_t)((m >> 7) * 32 + (k0 >> 5)) * TB
                     + (m & 127) * 80 + (k0 & 31) * 2;
    *(uint4*)(o + off) = *(uint4*)H;
}

__global__ __launch_bounds__(256)
void cvt3(const float* x0, const float* x1, const float* x2,
          char* o0, char* o1, char* o2)
{
    const int z = blockIdx.z;
    const float* x = (z == 0) ? x0 : (z == 1) ? x1 : x2;
    char* o = (z == 0) ? o0 : (z == 1) ? o1 : o2;
    cvt_one(x, o, blockIdx.x * 256 + threadIdx.x);
}

__global__ __launch_bounds__(256)
void cvt4(const float* x0, const float* x1, const float* x2, const float* x3,
          char* o0, char* o1, char* o2, char* o3)
{
    const int z = blockIdx.z;
    const float* x = (z == 0) ? x0 : (z == 1) ? x1 : (z == 2) ? x2 : x3;
    char* o = (z == 0) ? o0 : (z == 1) ? o1 : (z == 2) ? o2 : o3;
    cvt_one(x, o, blockIdx.x * 256 + threadIdx.x);
}

// ---------------------------------------------------------------------------
// Fused QKV projection GEMM, CTA 128x128, 256 thr, 2 CTAs/SM (R15 shape),
// single-fp16 outputs (Q pre-scaled).  grid (8, 64, 3).
// ---------------------------------------------------------------------------
#define GST1 (2 * TB)                 // 20480
#define SMEM_G1 (3 * GST1 + 64)       // 61504

struct QKVArgs {
    const char* A[3];
    const char* W[3];
    const float* bias[3];
    __half* O[3];
};

__global__ __launch_bounds__(256, 2)
void gemm_qkv(QKVArgs args)
{
    extern __shared__ __align__(16) char smem[];
    const uint32_t sb = smem_u32(smem);
    const uint32_t mbar = sb + 3 * GST1;

    const int z = blockIdx.z;
    const char* At = args.A[z];
    const char* Wt = args.W[z];
    const float* bias = args.bias[z];
    __half* O = args.O[z];

    const int tid  = threadIdx.x;
    const int lane = tid & 31;
    const int wid  = tid >> 5;
    const int wm   = wid & 1;
    const int wn   = wid >> 1;
    const int m0 = blockIdx.y * 128;
    const int n0 = blockIdx.x * 128;

    if (tid == 0) {
        MBARRIER_INIT(mbar, 1);
        MBARRIER_INIT(mbar + 8, 1);
        MBARRIER_INIT(mbar + 16, 1);
    }
    __syncthreads();

    auto issue = [&](int ks) {
        const int s = ks % 3;
        const uint32_t mb_ = mbar + s * 8;
        MBARRIER_EXPECT_TX(mb_, (uint32_t)GST1);
        bulk_g2s(sb + s * GST1,      At + (size_t)(blockIdx.y * 32 + ks) * TB, TB, mb_);
        bulk_g2s(sb + s * GST1 + TB, Wt + (size_t)(blockIdx.x * 32 + ks) * TB, TB, mb_);
    };

    float acc[4][4][4];
#pragma unroll
    for (int mi = 0; mi < 4; mi++)
#pragma unroll
        for (int ni = 0; ni < 4; ni++)
#pragma unroll
            for (int j = 0; j < 4; j++) acc[mi][ni][j] = 0.0f;

    if (tid == 0) { issue(0); issue(1); }
    int ph0 = 0, ph1 = 0, ph2 = 0;

    for (int ks = 0; ks < 32; ks++) {
        if (tid == 0 && ks + 2 < 32) issue(ks + 2);

        const int s = ks % 3;
        if (s == 0)      { MBARRIER_WAIT_PARITY(mbar,      ph0); ph0 ^= 1; }
        else if (s == 1) { MBARRIER_WAIT_PARITY(mbar + 8,  ph1); ph1 ^= 1; }
        else             { MBARRIER_WAIT_PARITY(mbar + 16, ph2); ph2 ^= 1; }

        const uint32_t sA = sb + s * GST1;
        const uint32_t sW = sA + TB;

#pragma unroll
        for (int kk = 0; kk < 32; kk += 16) {
            uint32_t bw[4][2];
#pragma unroll
            for (int np = 0; np < 2; np++) {
                const int g    = lane >> 3;
                const int brow = wn * 32 + np * 16 + ((g >> 1) << 3) + (lane & 7);
                const int bk   = kk + ((g & 1) << 3);
                uint32_t r[4];
                ldsm4(sW + brow * 80 + bk * 2, r);
                bw[2 * np][0] = r[0]; bw[2 * np][1] = r[1];
                bw[2 * np + 1][0] = r[2]; bw[2 * np + 1][1] = r[3];
            }
            const int arow_off = (lane & 15);
            const int ak = kk + ((lane >> 4) << 3);
#pragma unroll
            for (int mi = 0; mi < 4; mi++) {
                const int arow = wm * 64 + mi * 16 + arow_off;
                uint32_t af[4];
                ldsm4(sA + arow * 80 + ak * 2, af);
#pragma unroll
                for (int ni = 0; ni < 4; ni++)
                    mma16816(acc[mi][ni], af, bw[ni]);
            }
        }
        __syncthreads();
    }

#pragma unroll
    for (int mi = 0; mi < 4; mi++) {
#pragma unroll
        for (int ni = 0; ni < 4; ni++) {
            const int row0 = m0 + wm * 64 + mi * 16 + (lane >> 2);
            const int col  = n0 + wn * 32 + ni * 8 + 2 * (lane & 3);
            const float b0 = __ldg(bias + col);
            const float b1 = __ldg(bias + col + 1);
            float v00 = acc[mi][ni][0] + b0, v01 = acc[mi][ni][1] + b1;
            float v10 = acc[mi][ni][2] + b0, v11 = acc[mi][ni][3] + b1;
            if (z == 0) {       // Q: fold softmax scale * log2(e)
                v00 *= QSCALE; v01 *= QSCALE; v10 *= QSCALE; v11 *= QSCALE;
            }
            const int h = col >> 6, k = col & 63;
            {
                const int b = row0 >> 11, srow = row0 & 2047;
                const size_t o = (((size_t)b * HH + h) * SS + srow) * DK + k;
                *(uint32_t*)(O + o) = pack2h(v00, v01);
            }
            {
                const int r1 = row0 + 8;
                const int b = r1 >> 11, srow = r1 & 2047;
                const size_t o = (((size_t)b * HH + h) * SS + srow) * DK + k;
                *(uint32_t*)(O + o) = pack2h(v10, v11);
            }
        }
    }
}

// ---------------------------------------------------------------------------
// Output projection GEMM: C = Z x Wp^T + bias, single-fp16 Z (1 MMA/chunk),
// 3-stage bulk pipeline (2 x 10KB per stage), fp32 row-major out.
// ---------------------------------------------------------------------------
#define GST2 (2 * TB)                 // 20480
#define SMEM_G2 (3 * GST2 + 64)       // 61504

__global__ __launch_bounds__(256, 2)
void gemm_out(const char* __restrict__ At, const char* __restrict__ Wt,
              const float* __restrict__ bias, float* __restrict__ Cf)
{
    extern __shared__ __align__(16) char smem[];
    const uint32_t sb = smem_u32(smem);
    const uint32_t mbar = sb + 3 * GST2;

    const int tid  = threadIdx.x;
    const int lane = tid & 31;
    const int wid  = tid >> 5;
    const int wm   = wid & 1;
    const int wn   = wid >> 1;
    const int m0 = blockIdx.y * 128;
    const int n0 = blockIdx.x * 128;

    if (tid == 0) {
        MBARRIER_INIT(mbar, 1);
        MBARRIER_INIT(mbar + 8, 1);
        MBARRIER_INIT(mbar + 16, 1);
    }
    __syncthreads();

    auto issue = [&](int ks) {
        const int s = ks % 3;
        const uint32_t mb_ = mbar + s * 8;
        MBARRIER_EXPECT_TX(mb_, (uint32_t)GST2);
        bulk_g2s(sb + s * GST2,      At + (size_t)(blockIdx.y * 32 + ks) * TB, TB, mb_);
        bulk_g2s(sb + s * GST2 + TB, Wt + (size_t)(blockIdx.x * 32 + ks) * TB, TB, mb_);
    };

    float acc[4][4][4];
#pragma unroll
    for (int mi = 0; mi < 4; mi++)
#pragma unroll
        for (int ni = 0; ni < 4; ni++)
#pragma unroll
            for (int j = 0; j < 4; j++) acc[mi][ni][j] = 0.0f;

    if (tid == 0) { issue(0); issue(1); }
    int ph0 = 0, ph1 = 0, ph2 = 0;

    for (int ks = 0; ks < 32; ks++) {
        if (tid == 0 && ks + 2 < 32) issue(ks + 2);

        const int s = ks % 3;
        if (s == 0)      { MBARRIER_WAIT_PARITY(mbar,      ph0); ph0 ^= 1; }
        else if (s == 1) { MBARRIER_WAIT_PARITY(mbar + 8,  ph1); ph1 ^= 1; }
        else             { MBARRIER_WAIT_PARITY(mbar + 16, ph2); ph2 ^= 1; }

        const uint32_t sA = sb + s * GST2;
        const uint32_t sW = sA + TB;

#pragma unroll
        for (int kk = 0; kk < 32; kk += 16) {
            uint32_t bw[4][2];
#pragma unroll
            for (int np = 0; np < 2; np++) {
                const int g    = lane >> 3;
                const int brow = wn * 32 + np * 16 + ((g >> 1) << 3) + (lane & 7);
                const int bk   = kk + ((g & 1) << 3);
                uint32_t r[4];
                ldsm4(sW + brow * 80 + bk * 2, r);
                bw[2 * np][0] = r[0]; bw[2 * np][1] = r[1];
                bw[2 * np + 1][0] = r[2]; bw[2 * np + 1][1] = r[3];
            }
            const int arow_off = (lane & 15);
            const int ak = kk + ((lane >> 4) << 3);
#pragma unroll
            for (int mi = 0; mi < 4; mi++) {
                const int arow = wm * 64 + mi * 16 + arow_off;
                uint32_t af[4];
                ldsm4(sA + arow * 80 + ak * 2, af);
#pragma unroll
                for (int ni = 0; ni < 4; ni++)
                    mma16816(acc[mi][ni], af, bw[ni]);
            }
        }
        __syncthreads();
    }

#pragma unroll
    for (int mi = 0; mi < 4; mi++) {
#pragma unroll
        for (int ni = 0; ni < 4; ni++) {
            const int row0 = m0 + wm * 64 + mi * 16 + (lane >> 2);
            const int col  = n0 + wn * 32 + ni * 8 + 2 * (lane & 3);
            const float b0 = __ldg(bias + col);
            const float b1 = __ldg(bias + col + 1);
            *(float2*)(Cf + (size_t)row0 * DD + col) =
                make_float2(acc[mi][ni][0] + b0, acc[mi][ni][1] + b1);
            *(float2*)(Cf + (size_t)(row0 + 8) * DD + col) =
                make_float2(acc[mi][ni][2] + b0, acc[mi][ni][3] + b1);
        }
    }
}

// ---------------------------------------------------------------------------
// Causal flash attention: single-fp16 Q (1 MMA QK), single-fp16 P (1 MMA PV),
// fp32 ex2 softmax, single-fp16 Z epilogue.  4 CTAs/SM.  (R16 version)
// ---------------------------------------------------------------------------
#define ROWB 144
#define KVTILE (64 * ROWB)
#define STGATT (2 * KVTILE)
#define SMEM_ATT (2 * STGATT)

__global__ __launch_bounds__(128, 4)
void attn_mma()
{
    extern __shared__ __align__(16) char smem[];
    const uint32_t sb = smem_u32(smem);
    const int tid  = threadIdx.x;
    const int lane = tid & 31;
    const int w    = tid >> 5;
    const int qb   = gridDim.x - 1 - blockIdx.x;   // big tiles first
    const int bh   = blockIdx.y;

    const size_t hoff = (size_t)bh * SS * DK;
    const __half* kvsrc[2] = { g_KP + hoff, g_VP + hoff };

    auto load_kv = [&](int kb, int stage) {
        const size_t base = (size_t)kb * 64 * DK;
#pragma unroll
        for (int i = 0; i < 8; i++) {
            const int c   = tid + i * 128;
            const int t   = c >> 9;
            const int cc  = c & 511;
            const int row = cc >> 3;
            const int ch  = cc & 7;
            cp16(sb + stage * STGATT + t * KVTILE + row * ROWB + ch * 16,
                 kvsrc[t] + base + row * DK + ch * 8);
        }
    };

    // prologue: Q (single tile) into stage-1 area, KV block 0 into stage 0
    {
        const __half* qsrc = g_QP + hoff + (size_t)qb * 64 * DK;
#pragma unroll
        for (int i = 0; i < 4; i++) {
            const int c   = tid + i * 128;
            const int row = c >> 3;
            const int ch  = c & 7;
            cp16(sb + STGATT + row * ROWB + ch * 16, qsrc + row * DK + ch * 8);
        }
    }
    CP_COMMIT;
    load_kv(0, 0);
    CP_COMMIT;
    CP_WAIT1;
    __syncthreads();

    uint32_t qf[4][4];
#pragma unroll
    for (int kc = 0; kc < 4; kc++) {
        const int row = w * 16 + (lane & 15);
        const int k   = kc * 16 + ((lane >> 4) << 3);
        ldsm4(sb + STGATT + row * ROWB + k * 2, qf[kc]);
    }
    __syncthreads();

    float co[8][4];
#pragma unroll
    for (int n = 0; n < 8; n++)
#pragma unroll
        for (int j = 0; j < 4; j++) co[n][j] = 0.0f;
    float m0v = -1e30f, m1v = -1e30f, l0 = 0.0f, l1 = 0.0f;

    for (int kb = 0; kb <= qb; kb++) {
        CP_WAIT0;
        __syncthreads();
        if (kb < qb) {
            load_kv(kb + 1, (kb + 1) & 1);
            CP_COMMIT;
        }

        const uint32_t stb = sb + (kb & 1) * STGATT;

        float c[8][4];
#pragma unroll
        for (int n = 0; n < 8; n++)
#pragma unroll
            for (int j = 0; j < 4; j++) c[n][j] = 0.0f;

#pragma unroll
        for (int kc = 0; kc < 4; kc++) {
            uint32_t kf[8][2];
#pragma unroll
            for (int p = 0; p < 4; p++) {
                const int g    = lane >> 3;
                const int brow = p * 16 + ((g >> 1) << 3) + (lane & 7);
                const int bk   = kc * 16 + ((g & 1) << 3);
                uint32_t r[4];
                ldsm4(stb + brow * ROWB + bk * 2, r);
                kf[2 * p][0] = r[0]; kf[2 * p][1] = r[1];
                kf[2 * p + 1][0] = r[2]; kf[2 * p + 1][1] = r[3];
            }
#pragma unroll
            for (int n = 0; n < 8; n++)
                mma16816(c[n], qf[kc], kf[n]);
        }

        // ---- softmax in log2 domain (scale pre-folded into Q) ----
        const bool diag = (kb == qb);
        const int r0 = lane >> 2, r1 = r0 + 8;
        const int rowloc = w * 16;
        float mx0 = -1e30f, mx1 = -1e30f;
#pragma unroll
        for (int n = 0; n < 8; n++) {
            if (diag) {
#pragma unroll
                for (int j = 0; j < 4; j++) {
                    const int col = n * 8 + 2 * (lane & 3) + (j & 1);
                    const int row = rowloc + ((j < 2) ? r0 : r1);
                    if (col > row) c[n][j] = -1e30f;
                }
            }
            mx0 = fmaxf(mx0, fmaxf(c[n][0], c[n][1]));
            mx1 = fmaxf(mx1, fmaxf(c[n][2], c[n][3]));
        }
        mx0 = fmaxf(mx0, __shfl_xor_sync(0xffffffff, mx0, 1));
        mx0 = fmaxf(mx0, __shfl_xor_sync(0xffffffff, mx0, 2));
        mx1 = fmaxf(mx1, __shfl_xor_sync(0xffffffff, mx1, 1));
        mx1 = fmaxf(mx1, __shfl_xor_sync(0xffffffff, mx1, 2));

        const float mn0 = fmaxf(m0v, mx0), mn1 = fmaxf(m1v, mx1);
        const float cor0 = ex2f(m0v - mn0), cor1 = ex2f(m1v - mn1);
        m0v = mn0; m1v = mn1;

        float s0 = 0.0f, s1 = 0.0f;
#pragma unroll
        for (int n = 0; n < 8; n++) {
            c[n][0] = ex2f(c[n][0] - mn0);
            c[n][1] = ex2f(c[n][1] - mn0);
            c[n][2] = ex2f(c[n][2] - mn1);
            c[n][3] = ex2f(c[n][3] - mn1);
            s0 += c[n][0] + c[n][1];
            s1 += c[n][2] + c[n][3];
        }
        s0 += __shfl_xor_sync(0xffffffff, s0, 1);
        s0 += __shfl_xor_sync(0xffffffff, s0, 2);
        s1 += __shfl_xor_sync(0xffffffff, s1, 1);
        s1 += __shfl_xor_sync(0xffffffff, s1, 2);
        l0 = l0 * cor0 + s0;
        l1 = l1 * cor1 + s1;
#pragma unroll
        for (int n = 0; n < 8; n++) {
            co[n][0] *= cor0; co[n][1] *= cor0;
            co[n][2] *= cor1; co[n][3] *= cor1;
        }

        // ---- pack P as single fp16 A-fragments ----
        uint32_t pa[4][4];
#pragma unroll
        for (int kc = 0; kc < 4; kc++) {
            pa[kc][0] = pack2h(c[2 * kc][0],     c[2 * kc][1]);
            pa[kc][1] = pack2h(c[2 * kc][2],     c[2 * kc][3]);
            pa[kc][2] = pack2h(c[2 * kc + 1][0], c[2 * kc + 1][1]);
            pa[kc][3] = pack2h(c[2 * kc + 1][2], c[2 * kc + 1][3]);
        }

#pragma unroll
        for (int kc = 0; kc < 4; kc++) {
            uint32_t vf[8][2];
#pragma unroll
            for (int dp = 0; dp < 4; dp++) {
                const int g    = lane >> 3;
                const int j    = lane & 7;
                const int srow = kc * 16 + ((g & 1) << 3) + j;
                const int dcol = dp * 16 + ((g >> 1) << 3);
                uint32_t r[4];
                ldsm4t(stb + KVTILE + srow * ROWB + dcol * 2, r);
                vf[2 * dp][0] = r[0]; vf[2 * dp][1] = r[1];
                vf[2 * dp + 1][0] = r[2]; vf[2 * dp + 1][1] = r[3];
            }
#pragma unroll
            for (int n = 0; n < 8; n++)
                mma16816(co[n], pa[kc], vf[n]);
        }
    }

    // epilogue: write Z tiled as single fp16 for the output GEMM
    const float i0 = 1.0f / l0, i1 = 1.0f / l1;
    const int b  = bh >> 4;
    const int hh = bh & 15;
    const int q0 = qb * 64 + w * 16 + (lane >> 2);
#pragma unroll
    for (int n = 0; n < 8; n++) {
        const int dk  = n * 8 + 2 * (lane & 3);
        const int col = hh * 64 + dk;
        const int mA = b * SS + q0;
        const int mB = mA + 8;
        const size_t oA = (size_t)((mA >> 7) * 32 + (col >> 5)) * TB
                        + (mA & 127) * 80 + (col & 31) * 2;
        const size_t oB = (size_t)((mB >> 7) * 32 + (col >> 5)) * TB
                        + (mB & 127) * 80 + (col & 31) * 2;
        *(uint32_t*)(g_ZT + oA) = pack2h(co[n][0] * i0, co[n][1] * i0);
        *(uint32_t*)(g_ZT + oB) = pack2h(co[n][2] * i1, co[n][3] * i1);
    }
}

// ---------------------------------------------------------------------------
// Launch
// ---------------------------------------------------------------------------
extern "C" void kernel_launch(void* const* d_in, const int* in_sizes, int n_in,
                              void* d_out, int out_size)
{
    const float* query = (const float*)d_in[0];
    const float* key   = (const float*)d_in[1];
    const float* value = (const float*)d_in[2];
    const float* Wq    = (const float*)d_in[3];
    const float* bq    = (const float*)d_in[4];
    const float* Wk    = (const float*)d_in[5];
    const float* bk    = (const float*)d_in[6];
    const float* Wv    = (const float*)d_in[7];
    const float* bv    = (const float*)d_in[8];
    const float* Wp    = (const float*)d_in[9];
    const float* bp    = (const float*)d_in[10];
    // d_in[11] = mask (statically causal -> applied analytically)

    char *qT, *kT, *vT, *ZT, *WqT, *WkT, *WvT, *WpT;
    __half *QP, *KP, *VP;
    cudaGetSymbolAddress((void**)&qT, g_qT);
    cudaGetSymbolAddress((void**)&kT, g_kT);
    cudaGetSymbolAddress((void**)&vT, g_vT);
    cudaGetSymbolAddress((void**)&ZT, g_ZT);
    cudaGetSymbolAddress((void**)&WqT, g_WqT); cudaGetSymbolAddress((void**)&WkT, g_WkT);
    cudaGetSymbolAddress((void**)&WvT, g_WvT); cudaGetSymbolAddress((void**)&WpT, g_WpT);
    cudaGetSymbolAddress((void**)&QP, g_QP);
    cudaGetSymbolAddress((void**)&KP, g_KP);
    cudaGetSymbolAddress((void**)&VP, g_VP);

    cudaFuncSetAttribute(gemm_qkv, cudaFuncAttributeMaxDynamicSharedMemorySize, SMEM_G1);
    cudaFuncSetAttribute(gemm_out, cudaFuncAttributeMaxDynamicSharedMemorySize, SMEM_G2);
    cudaFuncSetAttribute(attn_mma, cudaFuncAttributeMaxDynamicSharedMemorySize, SMEM_ATT);

    QKVArgs qa;
    qa.A[0] = qT;  qa.A[1] = kT;  qa.A[2] = vT;
    qa.W[0] = WqT; qa.W[1] = WkT; qa.W[2] = WvT;
    qa.bias[0] = bq; qa.bias[1] = bk; qa.bias[2] = bv;
    qa.O[0] = QP; qa.O[1] = KP; qa.O[2] = VP;

    cvt4<<<dim3(DD * DD / 8 / 256, 1, 4), 256>>>(Wq, Wk, Wv, Wp,
                                                 WqT, WkT, WvT, WpT);
    cvt3<<<dim3(MTOT * DD / 8 / 256, 1, 3), 256>>>(query, key, value,
                                                   qT, kT, vT);
    gemm_qkv<<<dim3(DD / 128, MTOT / 128, 3), 256, SMEM_G1>>>(qa);
    attn_mma<<<dim3(SS / 64, BB * HH), 128, SMEM_ATT>>>();
    gemm_out<<<dim3(DD / 128, MTOT / 128), 256, SMEM_G2>>>(ZT, WpT, bp,
                                                           (float*)d_out);
}